// round 13
// baseline (speedup 1.0000x reference)
#include <cuda_runtime.h>
#include <cuda_fp16.h>
#include <cstdint>

// ---------------- problem constants ----------------
#define B_ROWS 16384
#define H_DIM  1024
#define DEEP_IN 205
#define K1_PAD 256          // W1 storage stride; live K = 208 (13 k16 steps)
#define ND_DIM 13

// Wide offsets (reference: cross = cross*F + s, F=3)
#define OFF_PAIR01  768
#define OFF_PAIR02  (768 + 65536)
#define OFF_PAIR12  (768 + 131072)
#define OFF_TRIPLE  (768 + 196608)
#define OFF_DENSE   16974592

#define NSLICE 16   // (H/128) * 2 wn strips

// ---------------- device scratch ----------------
__device__ __half g_emb_h[3 * 256 * 64];              // fp16 embedding tables
__device__ __half g_dense_h[(size_t)B_ROWS * 64];     // dense padded to 64 cols
__device__ __half g_w1h[(size_t)H_DIM * K1_PAD];
__device__ __half g_w2h[(size_t)H_DIM * H_DIM];
__device__ float  g_wide[B_ROWS];
__device__ __half g_h1[(size_t)B_ROWS * H_DIM];
__device__ float  g_part[NSLICE * B_ROWS];

// sync counters: [0]=prep1, [1]=prep2, [2..129]=band1[bm], [130..257]=band2[bm]
__device__ int g_ctr[258];

// ---------------- phase layout ----------------
// Quarter-wave prep phases so prep overlaps gemm1 inside wave 1
// (R12 lesson: 296-CTA prep phases serialized into whole waves).
#define NPREP1 74
#define NPREP2 74
#define G1_BASE (NPREP1 + NPREP2)       // 148
#define G2_BASE (G1_BASE + 1024)        // 1172
#define FIN_BASE (G2_BASE + 1024)       // 2196
#define TOTAL_CTAS (FIN_BASE + 64)      // 2260

// ---------------- helpers ----------------
__device__ __forceinline__ uint32_t smem_u32(const void* p) {
    uint32_t a;
    asm("{ .reg .u64 t; cvta.to.shared.u64 t, %1; cvt.u32.u64 %0, t; }" : "=r"(a) : "l"(p));
    return a;
}
__device__ __forceinline__ void cp_async16(uint32_t saddr, const void* gptr) {
    asm volatile("cp.async.cg.shared.global [%0], [%1], 16;\n" :: "r"(saddr), "l"(gptr));
}
__device__ __forceinline__ void cp_commit() { asm volatile("cp.async.commit_group;\n"); }

__device__ __forceinline__ void ldsm_x4(uint32_t& r0, uint32_t& r1, uint32_t& r2, uint32_t& r3,
                                        uint32_t addr) {
    asm volatile("ldmatrix.sync.aligned.m8n8.x4.shared.b16 {%0,%1,%2,%3}, [%4];"
                 : "=r"(r0), "=r"(r1), "=r"(r2), "=r"(r3) : "r"(addr));
}

__device__ __forceinline__ void arrive_ctr(int idx) {
    __syncthreads();
    __threadfence();
    if (threadIdx.x == 0) atomicAdd(&g_ctr[idx], 1);
}
__device__ __forceinline__ void wait_ctr(int idx, int target) {
    if (threadIdx.x == 0) {
        volatile int* c = &g_ctr[idx];
        while (*c < target) __nanosleep(128);
    }
    __syncthreads();
    __threadfence();
}

// ---------------- shared GEMM config ----------------
#define BK 64
#define ROWB 144
#define A_BYTES (128 * ROWB)               // 18432
#define STAGE_BYTES (2 * A_BYTES)          // 36864
#define NSTAGE 3
#define SMEM_BYTES (NSTAGE * STAGE_BYTES)  // 110592

#define MMA_BLOCK(acc, af, bf) \
    _Pragma("unroll") \
    for (int im = 0; im < 2; im++) \
        _Pragma("unroll") \
        for (int jn = 0; jn < 8; jn++) { \
            asm volatile( \
                "mma.sync.aligned.m16n8k16.row.col.f32.f16.f16.f32 " \
                "{%0,%1,%2,%3},{%4,%5,%6,%7},{%8,%9},{%0,%1,%2,%3};\n" \
                : "+f"((acc)[im][jn][0]), "+f"((acc)[im][jn][1]), \
                  "+f"((acc)[im][jn][2]), "+f"((acc)[im][jn][3]) \
                : "r"((af)[im][0]), "r"((af)[im][1]), "r"((af)[im][2]), "r"((af)[im][3]), \
                  "r"((bf)[jn][0]), "r"((bf)[jn][1])); \
        }

// ---------------- counter zeroing (launched before mega) ----------------
__global__ void zero_ctr_kernel() {
    if (threadIdx.x < 258) g_ctr[threadIdx.x] = 0;
}

// ---------------- mega kernel: all phases, flag-synced ----------------
__global__ __launch_bounds__(256, 2)
void mega_kernel(const float* __restrict__ W1,
                 const float* __restrict__ W2,
                 const int* __restrict__ sparse,
                 const float* __restrict__ dense,
                 const float* __restrict__ wide_w,
                 const float* __restrict__ wide_b,
                 const float* __restrict__ emb,
                 const float* __restrict__ b1,
                 const float* __restrict__ b2,
                 const float* __restrict__ W3,
                 const float* __restrict__ b3,
                 float* __restrict__ out) {
    extern __shared__ char smem[];
    int bid = blockIdx.x;
    int tid = threadIdx.x;

    // ======== PREP1: w1h, emb_h, dense_h ========
    if (bid < NPREP1) {
        const int stride = NPREP1 * 256;
        int base = bid * 256 + tid;
        for (int idx = base; idx < H_DIM * K1_PAD; idx += stride) {
            int n = idx >> 8, k = idx & 255;
            g_w1h[idx] = __float2half((k < DEEP_IN) ? W1[n * DEEP_IN + k] : 0.0f);
        }
        for (int idx = base; idx < 3 * 256 * 32; idx += stride) {
            float2 v = *reinterpret_cast<const float2*>(emb + idx * 2);
            *reinterpret_cast<__half2*>(g_emb_h + idx * 2) = __floats2half2_rn(v.x, v.y);
        }
        for (int idx = base; idx < B_ROWS * 32; idx += stride) {
            int row = idx >> 5, c2 = idx & 31;
            int c0 = c2 * 2, c1 = c0 + 1;
            float v0 = (c0 < ND_DIM) ? dense[row * ND_DIM + c0] : 0.0f;
            float v1 = (c1 < ND_DIM) ? dense[row * ND_DIM + c1] : 0.0f;
            *reinterpret_cast<__half2*>(g_dense_h + (size_t)row * 64 + c0) = __floats2half2_rn(v0, v1);
        }
        arrive_ctr(0);
        return;
    }

    // ======== PREP2: w2h, wide scalar (overlaps gemm1) ========
    if (bid < G1_BASE) {
        const int stride = NPREP2 * 256;
        int base = (bid - NPREP1) * 256 + tid;
        for (int idx = base; idx < H_DIM * H_DIM / 2; idx += stride) {
            float2 v = *reinterpret_cast<const float2*>(W2 + idx * 2);
            *reinterpret_cast<__half2*>(g_w2h + idx * 2) = __floats2half2_rn(v.x, v.y);
        }
        for (int row = base; row < B_ROWS; row += stride) {
            int s0 = sparse[row * 3 + 0];
            int s1 = sparse[row * 3 + 1];
            int s2 = sparse[row * 3 + 2];
            float w = wide_b[0];
            w += wide_w[s0] + wide_w[256 + s1] + wide_w[512 + s2];
            w += wide_w[OFF_PAIR01 + s0 * 3 + s1];
            w += wide_w[OFF_PAIR02 + s0 * 3 + s2];
            w += wide_w[OFF_PAIR12 + s1 * 3 + s2];
            w += wide_w[OFF_TRIPLE + (s0 * 3 + s1) * 3 + s2];
            const float* dw = wide_w + OFF_DENSE;
            float acc = 0.0f;
            #pragma unroll
            for (int j = 0; j < ND_DIM; j++) acc += dense[row * ND_DIM + j] * dw[j];
            g_wide[row] = w + acc;
        }
        arrive_ctr(1);
        return;
    }

    uint32_t sb = smem_u32(smem);
    int lane = tid & 31;
    int warp = tid >> 5;
    int wm = warp & 3;
    int wn = warp >> 2;
    int lrow = lane & 7;
    int lmat = lane >> 3;
    uint32_t aoff0 = (uint32_t)((wm * 32 + ((lmat & 1) << 3) + lrow) * ROWB + ((lmat >> 1) << 4));
    uint32_t boff0 = (uint32_t)((wn * 64 + ((lmat >> 1) << 3) + lrow) * ROWB + ((lmat & 1) << 4));

    // ======== GEMM1: h1 = relu(deepx @ W1^T + b1), A gathered from tables ========
    if (bid < G2_BASE) {
        int g = bid - G1_BASE;
        int bm = g >> 3, bn = g & 7;        // bm-major: bands complete in order

        wait_ctr(0, NPREP1);

        float acc[2][8][4];
        #pragma unroll
        for (int i = 0; i < 2; i++)
            #pragma unroll
            for (int j = 0; j < 8; j++)
                #pragma unroll
                for (int q = 0; q < 4; q++) acc[i][j][q] = 0.0f;

        const __half* Bg = g_w1h + (size_t)(bn * 128) * K1_PAD;

        auto load_stage = [&](int slot, int kt_i) {
            uint32_t sA = sb + slot * STAGE_BYTES;
            uint32_t sB = sA + A_BYTES;
            #pragma unroll
            for (int i = 0; i < 8; i++) {
                int idx = i * 256 + tid;
                if (idx < 1024) {
                    int r = idx >> 3, c = idx & 7;
                    const __half* src;
                    if (kt_i < 3) {
                        int s = sparse[(bm * 128 + r) * 3 + kt_i];
                        src = g_emb_h + ((kt_i << 8) + s) * 64 + c * 8;
                    } else {
                        src = g_dense_h + (size_t)(bm * 128 + r) * 64 + c * 8;
                    }
                    cp_async16(sA + r * ROWB + c * 16, src);
                } else {
                    int j = idx - 1024;
                    int r = j >> 3, c = j & 7;
                    cp_async16(sB + r * ROWB + c * 16, Bg + (size_t)r * K1_PAD + kt_i * BK + c * 8);
                }
            }
            cp_commit();
        };

        load_stage(0, 0);
        load_stage(1, 1);

        int slot = 0, slot2 = 2;
        for (int kt = 0; kt < 4; kt++) {
            asm volatile("cp.async.wait_group 1;\n" ::: "memory");
            __syncthreads();

            if (kt + 2 < 4) load_stage(slot2, kt + 2);
            else cp_commit();

            uint32_t sA = sb + slot * STAGE_BYTES;
            uint32_t sB = sA + A_BYTES;

            int ks_n = (kt < 3) ? 4 : 1;   // tail tile: only k16 step 0 live
            for (int ks = 0; ks < ks_n; ks++) {
                uint32_t af[2][4];
                #pragma unroll
                for (int im = 0; im < 2; im++)
                    ldsm_x4(af[im][0], af[im][1], af[im][2], af[im][3],
                            sA + aoff0 + im * (16 * ROWB) + ks * 32);
                uint32_t bf[8][2];
                #pragma unroll
                for (int p = 0; p < 4; p++) {
                    uint32_t q0, q1, q2, q3;
                    ldsm_x4(q0, q1, q2, q3, sB + boff0 + p * (16 * ROWB) + ks * 32);
                    bf[2 * p][0] = q0; bf[2 * p][1] = q1;
                    bf[2 * p + 1][0] = q2; bf[2 * p + 1][1] = q3;
                }
                MMA_BLOCK(acc, af, bf);
            }

            slot = (slot == NSTAGE - 1) ? 0 : slot + 1;
            slot2 = (slot2 == NSTAGE - 1) ? 0 : slot2 + 1;
        }

        int nbase = bn * 128 + wn * 64 + 2 * (lane & 3);
        #pragma unroll
        for (int im = 0; im < 2; im++) {
            #pragma unroll
            for (int jn = 0; jn < 8; jn++) {
                int m0 = bm * 128 + wm * 32 + im * 16 + (lane >> 2);
                int n0 = nbase + jn * 8;
                float bv0 = __ldg(b1 + n0), bv1 = __ldg(b1 + n0 + 1);
                float v0 = fmaxf(acc[im][jn][0] + bv0, 0.0f);
                float v1 = fmaxf(acc[im][jn][1] + bv1, 0.0f);
                float v2 = fmaxf(acc[im][jn][2] + bv0, 0.0f);
                float v3 = fmaxf(acc[im][jn][3] + bv1, 0.0f);
                *reinterpret_cast<__half2*>(&g_h1[(size_t)m0 * H_DIM + n0]) = __floats2half2_rn(v0, v1);
                *reinterpret_cast<__half2*>(&g_h1[(size_t)(m0 + 8) * H_DIM + n0]) = __floats2half2_rn(v2, v3);
            }
        }
        arrive_ctr(2 + bm);
        return;
    }

    // ======== GEMM2: fused relu + W3 dot -> partials ========
    if (bid < FIN_BASE) {
        int g = bid - G2_BASE;
        int bm = g >> 3, bn = g & 7;

        wait_ctr(1, NPREP2);         // w2h ready
        wait_ctr(2 + bm, 8);         // h1 band ready

        const __half* Ag = g_h1 + (size_t)(bm * 128) * H_DIM;
        const __half* Bg = g_w2h + (size_t)(bn * 128) * H_DIM;

        float acc[2][8][4];
        #pragma unroll
        for (int i = 0; i < 2; i++)
            #pragma unroll
            for (int j = 0; j < 8; j++)
                #pragma unroll
                for (int q = 0; q < 4; q++) acc[i][j][q] = 0.0f;

        auto load_stage = [&](int slot, int k0) {
            uint32_t sA = sb + slot * STAGE_BYTES;
            uint32_t sB = sA + A_BYTES;
            #pragma unroll
            for (int i = 0; i < 8; i++) {
                int idx = i * 256 + tid;
                if (idx < 1024) {
                    int r = idx >> 3, c = idx & 7;
                    cp_async16(sA + r * ROWB + c * 16, Ag + (size_t)r * H_DIM + k0 + c * 8);
                } else {
                    int j = idx - 1024;
                    int r = j >> 3, c = j & 7;
                    cp_async16(sB + r * ROWB + c * 16, Bg + (size_t)r * H_DIM + k0 + c * 8);
                }
            }
            cp_commit();
        };

        load_stage(0, 0);
        load_stage(1, BK);

        const int KT = H_DIM / BK;   // 16
        int slot = 0, slot2 = 2;
        for (int kt = 0; kt < KT; kt++) {
            asm volatile("cp.async.wait_group 1;\n" ::: "memory");
            __syncthreads();

            if (kt + 2 < KT) load_stage(slot2, (kt + 2) * BK);
            else cp_commit();

            uint32_t sA = sb + slot * STAGE_BYTES;
            uint32_t sB = sA + A_BYTES;

            #pragma unroll
            for (int ks = 0; ks < 4; ks++) {
                uint32_t af[2][4];
                #pragma unroll
                for (int im = 0; im < 2; im++)
                    ldsm_x4(af[im][0], af[im][1], af[im][2], af[im][3],
                            sA + aoff0 + im * (16 * ROWB) + ks * 32);
                uint32_t bf[8][2];
                #pragma unroll
                for (int p = 0; p < 4; p++) {
                    uint32_t q0, q1, q2, q3;
                    ldsm_x4(q0, q1, q2, q3, sB + boff0 + p * (16 * ROWB) + ks * 32);
                    bf[2 * p][0] = q0; bf[2 * p][1] = q1;
                    bf[2 * p + 1][0] = q2; bf[2 * p + 1][1] = q3;
                }
                MMA_BLOCK(acc, af, bf);
            }

            slot = (slot == NSTAGE - 1) ? 0 : slot + 1;
            slot2 = (slot2 == NSTAGE - 1) ? 0 : slot2 + 1;
        }

        int nbase = bn * 128 + wn * 64 + 2 * (lane & 3);
        float pr[4] = {0.0f, 0.0f, 0.0f, 0.0f};
        #pragma unroll
        for (int jn = 0; jn < 8; jn++) {
            int n0 = nbase + jn * 8;
            float bv0 = __ldg(b2 + n0), bv1 = __ldg(b2 + n0 + 1);
            float w0 = __ldg(W3 + n0), w1 = __ldg(W3 + n0 + 1);
            #pragma unroll
            for (int im = 0; im < 2; im++) {
                float v0 = fmaxf(acc[im][jn][0] + bv0, 0.0f);
                float v1 = fmaxf(acc[im][jn][1] + bv1, 0.0f);
                float v2 = fmaxf(acc[im][jn][2] + bv0, 0.0f);
                float v3 = fmaxf(acc[im][jn][3] + bv1, 0.0f);
                pr[2 * im + 0] += v0 * w0 + v1 * w1;
                pr[2 * im + 1] += v2 * w0 + v3 * w1;
            }
        }
        #pragma unroll
        for (int q = 0; q < 4; q++) {
            pr[q] += __shfl_xor_sync(0xffffffffu, pr[q], 1);
            pr[q] += __shfl_xor_sync(0xffffffffu, pr[q], 2);
        }
        if ((lane & 3) == 0) {
            int slice = bn * 2 + wn;
            int rbase = bm * 128 + wm * 32 + (lane >> 2);
            float* pp = g_part + (size_t)slice * B_ROWS + rbase;
            pp[0]  = pr[0];
            pp[8]  = pr[1];
            pp[16] = pr[2];
            pp[24] = pr[3];
        }
        arrive_ctr(130 + bm);
        return;
    }

    // ======== FINAL: combine + sigmoid ========
    {
        int f = bid - FIN_BASE;
        wait_ctr(1, NPREP2);             // g_wide ready
        wait_ctr(130 + 2 * f, 8);
        wait_ctr(130 + 2 * f + 1, 8);

        int row = f * 256 + tid;
        float z = g_wide[row] + b3[0];
        #pragma unroll
        for (int s = 0; s < NSLICE; s++) z += g_part[(size_t)s * B_ROWS + row];
        out[row] = 1.0f / (1.0f + expf(-z));
    }
}

// ---------------- launch ----------------
extern "C" void kernel_launch(void* const* d_in, const int* in_sizes, int n_in,
                              void* d_out, int out_size) {
    const int*   sparse = (const int*)d_in[0];
    const float* dense  = (const float*)d_in[1];
    const float* wide_w = (const float*)d_in[2];
    const float* wide_b = (const float*)d_in[3];
    const float* emb    = (const float*)d_in[4];
    const float* W1     = (const float*)d_in[5];
    const float* b1     = (const float*)d_in[6];
    const float* W2     = (const float*)d_in[7];
    const float* b2     = (const float*)d_in[8];
    const float* W3     = (const float*)d_in[9];
    const float* b3     = (const float*)d_in[10];
    float* out = (float*)d_out;

    cudaFuncSetAttribute(mega_kernel, cudaFuncAttributeMaxDynamicSharedMemorySize, SMEM_BYTES);

    zero_ctr_kernel<<<1, 258>>>();
    mega_kernel<<<TOTAL_CTAS, 256, SMEM_BYTES>>>(W1, W2, sparse, dense, wide_w, wide_b, emb,
                                                 b1, b2, W3, b3, out);
}

// round 14
// speedup vs baseline: 1.6229x; 1.6229x over previous
#include <cuda_runtime.h>
#include <cuda_fp16.h>
#include <cstdint>

// ---------------- problem constants ----------------
#define B_ROWS 16384
#define H_DIM  1024
#define DEEP_IN 205
#define K1_PAD 256          // W1 storage stride; live K = 208 (13 k16 steps)
#define ND_DIM 13

// Wide offsets (reference: cross = cross*F + s, F=3)
#define OFF_PAIR01  768
#define OFF_PAIR02  (768 + 65536)
#define OFF_PAIR12  (768 + 131072)
#define OFF_TRIPLE  (768 + 196608)
#define OFF_DENSE   16974592

#define NSLICE 16   // (H/128) * 2 wn strips

// ---------------- device scratch ----------------
__device__ __half g_emb_h[3 * 256 * 64];              // fp16 embedding tables
__device__ __half g_dense_h[(size_t)B_ROWS * 64];     // dense padded to 64 cols
__device__ __half g_w1h[(size_t)H_DIM * K1_PAD];
__device__ __half g_w2h[(size_t)H_DIM * H_DIM];
__device__ float  g_wide[B_ROWS];
__device__ __half g_h1[(size_t)B_ROWS * H_DIM];
__device__ float  g_part[NSLICE * B_ROWS];

// ---------------- helpers ----------------
__device__ __forceinline__ uint32_t smem_u32(const void* p) {
    uint32_t a;
    asm("{ .reg .u64 t; cvta.to.shared.u64 t, %1; cvt.u32.u64 %0, t; }" : "=r"(a) : "l"(p));
    return a;
}
__device__ __forceinline__ void cp_async16(uint32_t saddr, const void* gptr) {
    asm volatile("cp.async.cg.shared.global [%0], [%1], 16;\n" :: "r"(saddr), "l"(gptr));
}
__device__ __forceinline__ void cp_commit() { asm volatile("cp.async.commit_group;\n"); }

__device__ __forceinline__ void ldsm_x4(uint32_t& r0, uint32_t& r1, uint32_t& r2, uint32_t& r3,
                                        uint32_t addr) {
    asm volatile("ldmatrix.sync.aligned.m8n8.x4.shared.b16 {%0,%1,%2,%3}, [%4];"
                 : "=r"(r0), "=r"(r1), "=r"(r2), "=r"(r3) : "r"(addr));
}

// ---------------- merged prep ----------------
// blocks: [padw1 | convw2 | convemb | dense_h | wide]
#define PADW1_BLOCKS   1024    // 256*1024/256
#define CONVW2_BLOCKS  2048    // 1024*1024/(256*2)
#define CONVEMB_BLOCKS 96      // 3*256*64/(256*2)
#define DENSEH_BLOCKS  2048    // 16384*32 half2 / 256
#define WIDE_BLOCKS    2048    // 8 rows per block

__global__ void prep_all_kernel(const float* __restrict__ W1,
                                const float* __restrict__ W2,
                                const int* __restrict__ sparse,
                                const float* __restrict__ dense,
                                const float* __restrict__ wide_w,
                                const float* __restrict__ wide_b,
                                const float* __restrict__ emb) {
    int b = blockIdx.x;
    if (b < PADW1_BLOCKS) {
        int idx = b * 256 + threadIdx.x;
        int n = idx >> 8;
        int k = idx & 255;
        g_w1h[idx] = __float2half((k < DEEP_IN) ? W1[n * DEEP_IN + k] : 0.0f);
        return;
    }
    b -= PADW1_BLOCKS;
    if (b < CONVW2_BLOCKS) {
        int idx = b * 256 + threadIdx.x;
        float2 v = *reinterpret_cast<const float2*>(W2 + idx * 2);
        *reinterpret_cast<__half2*>(g_w2h + idx * 2) = __floats2half2_rn(v.x, v.y);
        return;
    }
    b -= CONVW2_BLOCKS;
    if (b < CONVEMB_BLOCKS) {
        int idx = b * 256 + threadIdx.x;
        float2 v = *reinterpret_cast<const float2*>(emb + idx * 2);
        *reinterpret_cast<__half2*>(g_emb_h + idx * 2) = __floats2half2_rn(v.x, v.y);
        return;
    }
    b -= CONVEMB_BLOCKS;
    if (b < DENSEH_BLOCKS) {
        int idx = b * 256 + threadIdx.x;        // one half2 (2 cols)
        int row = idx >> 5;
        int c2 = idx & 31;
        int c0 = c2 * 2, c1 = c0 + 1;
        float v0 = (c0 < ND_DIM) ? dense[row * ND_DIM + c0] : 0.0f;
        float v1 = (c1 < ND_DIM) ? dense[row * ND_DIM + c1] : 0.0f;
        *reinterpret_cast<__half2*>(g_dense_h + (size_t)row * 64 + c0) = __floats2half2_rn(v0, v1);
        return;
    }
    b -= DENSEH_BLOCKS;
    {
        int local = threadIdx.x >> 5;
        int t = threadIdx.x & 31;
        int row = b * 8 + local;
        if (t == 0) {
            int s0 = sparse[row * 3 + 0];
            int s1 = sparse[row * 3 + 1];
            int s2 = sparse[row * 3 + 2];
            float w = wide_b[0];
            w += wide_w[s0] + wide_w[256 + s1] + wide_w[512 + s2];
            w += wide_w[OFF_PAIR01 + s0 * 3 + s1];
            w += wide_w[OFF_PAIR02 + s0 * 3 + s2];
            w += wide_w[OFF_PAIR12 + s1 * 3 + s2];
            w += wide_w[OFF_TRIPLE + (s0 * 3 + s1) * 3 + s2];
            const float* dw = wide_w + OFF_DENSE;
            float acc = 0.0f;
            #pragma unroll
            for (int j = 0; j < ND_DIM; j++) acc += dense[row * ND_DIM + j] * dw[j];
            g_wide[row] = w + acc;
        }
    }
}

// ---------------- shared GEMM config ----------------
#define BK 64
#define ROWB 144
#define A_BYTES (128 * ROWB)               // 18432
#define STAGE_BYTES (2 * A_BYTES)          // 36864
#define NSTAGE 3
#define SMEM_BYTES (NSTAGE * STAGE_BYTES)  // 110592

#define MMA_BLOCK(acc, af, bf) \
    _Pragma("unroll") \
    for (int im = 0; im < 2; im++) \
        _Pragma("unroll") \
        for (int jn = 0; jn < 8; jn++) { \
            asm volatile( \
                "mma.sync.aligned.m16n8k16.row.col.f32.f16.f16.f32 " \
                "{%0,%1,%2,%3},{%4,%5,%6,%7},{%8,%9},{%0,%1,%2,%3};\n" \
                : "+f"((acc)[im][jn][0]), "+f"((acc)[im][jn][1]), \
                  "+f"((acc)[im][jn][2]), "+f"((acc)[im][jn][3]) \
                : "r"((af)[im][0]), "r"((af)[im][1]), "r"((af)[im][2]), "r"((af)[im][3]), \
                  "r"((bf)[jn][0]), "r"((bf)[jn][1])); \
        }

// ---------------- layer-1 GEMM: A gathered from emb_h/dense_h ----------------
// A-tile kt<3: row r = emb_h[kt*256 + sparse[r][kt]][0:64]; kt==3: dense_h row.
// KT=4, tail tile runs 1 k16 step (live K=208). Epilogue: relu+bias -> h1 fp16.
__global__ __launch_bounds__(256, 2)
void gemm1_emb(const int* __restrict__ sparse,
               const float* __restrict__ bias,
               __half* __restrict__ C) {
    extern __shared__ char smem[];
    uint32_t sb = smem_u32(smem);

    int tid = threadIdx.x;
    int lane = tid & 31;
    int warp = tid >> 5;
    int wm = warp & 3;
    int wn = warp >> 2;
    int bn = blockIdx.x, bm = blockIdx.y;

    int lrow = lane & 7;
    int lmat = lane >> 3;
    uint32_t aoff0 = (uint32_t)((wm * 32 + ((lmat & 1) << 3) + lrow) * ROWB + ((lmat >> 1) << 4));
    uint32_t boff0 = (uint32_t)((wn * 64 + ((lmat >> 1) << 3) + lrow) * ROWB + ((lmat & 1) << 4));

    float acc[2][8][4];
    #pragma unroll
    for (int i = 0; i < 2; i++)
        #pragma unroll
        for (int j = 0; j < 8; j++)
            #pragma unroll
            for (int q = 0; q < 4; q++) acc[i][j][q] = 0.0f;

    const __half* Bg = g_w1h + (size_t)(bn * 128) * K1_PAD;

    auto load_stage = [&](int slot, int kt_i) {
        uint32_t sA = sb + slot * STAGE_BYTES;
        uint32_t sB = sA + A_BYTES;
        #pragma unroll
        for (int i = 0; i < 8; i++) {
            int idx = i * 256 + tid;
            if (idx < 1024) {
                int r = idx >> 3, c = idx & 7;
                const __half* src;
                if (kt_i < 3) {
                    int s = sparse[(bm * 128 + r) * 3 + kt_i];
                    src = g_emb_h + ((kt_i << 8) + s) * 64 + c * 8;
                } else {
                    src = g_dense_h + (size_t)(bm * 128 + r) * 64 + c * 8;
                }
                cp_async16(sA + r * ROWB + c * 16, src);
            } else {
                int j = idx - 1024;
                int r = j >> 3, c = j & 7;
                cp_async16(sB + r * ROWB + c * 16, Bg + (size_t)r * K1_PAD + kt_i * BK + c * 8);
            }
        }
        cp_commit();
    };

    load_stage(0, 0);
    load_stage(1, 1);

    int slot = 0, slot2 = 2;
    for (int kt = 0; kt < 4; kt++) {
        asm volatile("cp.async.wait_group 1;\n" ::: "memory");
        __syncthreads();

        if (kt + 2 < 4) load_stage(slot2, kt + 2);
        else cp_commit();

        uint32_t sA = sb + slot * STAGE_BYTES;
        uint32_t sB = sA + A_BYTES;

        int ks_n = (kt < 3) ? 4 : 1;     // tail tile: only k16 step 0 is live
        for (int ks = 0; ks < ks_n; ks++) {
            uint32_t af[2][4];
            #pragma unroll
            for (int im = 0; im < 2; im++)
                ldsm_x4(af[im][0], af[im][1], af[im][2], af[im][3],
                        sA + aoff0 + im * (16 * ROWB) + ks * 32);
            uint32_t bf[8][2];
            #pragma unroll
            for (int p = 0; p < 4; p++) {
                uint32_t q0, q1, q2, q3;
                ldsm_x4(q0, q1, q2, q3, sB + boff0 + p * (16 * ROWB) + ks * 32);
                bf[2 * p][0] = q0; bf[2 * p][1] = q1;
                bf[2 * p + 1][0] = q2; bf[2 * p + 1][1] = q3;
            }
            MMA_BLOCK(acc, af, bf);
        }

        slot = (slot == NSTAGE - 1) ? 0 : slot + 1;
        slot2 = (slot2 == NSTAGE - 1) ? 0 : slot2 + 1;
    }

    int nbase = bn * 128 + wn * 64 + 2 * (lane & 3);
    #pragma unroll
    for (int im = 0; im < 2; im++) {
        #pragma unroll
        for (int jn = 0; jn < 8; jn++) {
            int m0 = bm * 128 + wm * 32 + im * 16 + (lane >> 2);
            int n0 = nbase + jn * 8;
            float bv0 = __ldg(bias + n0), bv1 = __ldg(bias + n0 + 1);
            float v0 = fmaxf(acc[im][jn][0] + bv0, 0.0f);
            float v1 = fmaxf(acc[im][jn][1] + bv1, 0.0f);
            float v2 = fmaxf(acc[im][jn][2] + bv0, 0.0f);
            float v3 = fmaxf(acc[im][jn][3] + bv1, 0.0f);
            *reinterpret_cast<__half2*>(&C[(size_t)m0 * H_DIM + n0]) = __floats2half2_rn(v0, v1);
            *reinterpret_cast<__half2*>(&C[(size_t)(m0 + 8) * H_DIM + n0]) = __floats2half2_rn(v2, v3);
        }
    }
}

// ---------------- layer-2 GEMM (R8 structure, unchanged) ----------------
// fused per-row partial of relu(A*B^T + bias) . W3 -> part[NSLICE][B]
__global__ __launch_bounds__(256, 2)
void gemm2_tc(const __half* __restrict__ A,
              const __half* __restrict__ Bm,
              const float* __restrict__ bias,
              const float* __restrict__ W3,
              float* __restrict__ part) {
    extern __shared__ char smem[];
    uint32_t sb = smem_u32(smem);

    int tid = threadIdx.x;
    int lane = tid & 31;
    int warp = tid >> 5;
    int wm = warp & 3;
    int wn = warp >> 2;
    int bn = blockIdx.x, bm = blockIdx.y;

    const __half* Ag = A + (size_t)(bm * 128) * H_DIM;
    const __half* Bg = Bm + (size_t)(bn * 128) * H_DIM;

    int lrow = lane & 7;
    int lmat = lane >> 3;
    uint32_t aoff0 = (uint32_t)((wm * 32 + ((lmat & 1) << 3) + lrow) * ROWB + ((lmat >> 1) << 4));
    uint32_t boff0 = (uint32_t)((wn * 64 + ((lmat >> 1) << 3) + lrow) * ROWB + ((lmat & 1) << 4));

    float acc[2][8][4];
    #pragma unroll
    for (int i = 0; i < 2; i++)
        #pragma unroll
        for (int j = 0; j < 8; j++)
            #pragma unroll
            for (int q = 0; q < 4; q++) acc[i][j][q] = 0.0f;

    auto load_stage = [&](int slot, int k0) {
        uint32_t sA = sb + slot * STAGE_BYTES;
        uint32_t sB = sA + A_BYTES;
        #pragma unroll
        for (int i = 0; i < 8; i++) {
            int idx = i * 256 + tid;
            if (idx < 1024) {
                int r = idx >> 3, c = idx & 7;
                cp_async16(sA + r * ROWB + c * 16, Ag + (size_t)r * H_DIM + k0 + c * 8);
            } else {
                int j = idx - 1024;
                int r = j >> 3, c = j & 7;
                cp_async16(sB + r * ROWB + c * 16, Bg + (size_t)r * H_DIM + k0 + c * 8);
            }
        }
        cp_commit();
    };

    load_stage(0, 0);
    load_stage(1, BK);

    const int KT = H_DIM / BK;   // 16
    int slot = 0, slot2 = 2;
    for (int kt = 0; kt < KT; kt++) {
        asm volatile("cp.async.wait_group 1;\n" ::: "memory");
        __syncthreads();

        if (kt + 2 < KT) load_stage(slot2, (kt + 2) * BK);
        else cp_commit();

        uint32_t sA = sb + slot * STAGE_BYTES;
        uint32_t sB = sA + A_BYTES;

        #pragma unroll
        for (int ks = 0; ks < 4; ks++) {
            uint32_t af[2][4];
            #pragma unroll
            for (int im = 0; im < 2; im++)
                ldsm_x4(af[im][0], af[im][1], af[im][2], af[im][3],
                        sA + aoff0 + im * (16 * ROWB) + ks * 32);
            uint32_t bf[8][2];
            #pragma unroll
            for (int p = 0; p < 4; p++) {
                uint32_t q0, q1, q2, q3;
                ldsm_x4(q0, q1, q2, q3, sB + boff0 + p * (16 * ROWB) + ks * 32);
                bf[2 * p][0] = q0; bf[2 * p][1] = q1;
                bf[2 * p + 1][0] = q2; bf[2 * p + 1][1] = q3;
            }
            MMA_BLOCK(acc, af, bf);
        }

        slot = (slot == NSTAGE - 1) ? 0 : slot + 1;
        slot2 = (slot2 == NSTAGE - 1) ? 0 : slot2 + 1;
    }

    int nbase = bn * 128 + wn * 64 + 2 * (lane & 3);
    float pr[4] = {0.0f, 0.0f, 0.0f, 0.0f};
    #pragma unroll
    for (int jn = 0; jn < 8; jn++) {
        int n0 = nbase + jn * 8;
        float bv0 = __ldg(bias + n0), bv1 = __ldg(bias + n0 + 1);
        float w0 = __ldg(W3 + n0), w1 = __ldg(W3 + n0 + 1);
        #pragma unroll
        for (int im = 0; im < 2; im++) {
            float v0 = fmaxf(acc[im][jn][0] + bv0, 0.0f);
            float v1 = fmaxf(acc[im][jn][1] + bv1, 0.0f);
            float v2 = fmaxf(acc[im][jn][2] + bv0, 0.0f);
            float v3 = fmaxf(acc[im][jn][3] + bv1, 0.0f);
            pr[2 * im + 0] += v0 * w0 + v1 * w1;
            pr[2 * im + 1] += v2 * w0 + v3 * w1;
        }
    }
    #pragma unroll
    for (int q = 0; q < 4; q++) {
        pr[q] += __shfl_xor_sync(0xffffffffu, pr[q], 1);
        pr[q] += __shfl_xor_sync(0xffffffffu, pr[q], 2);
    }
    if ((lane & 3) == 0) {
        int slice = bn * 2 + wn;
        int rbase = bm * 128 + wm * 32 + (lane >> 2);
        float* pp = part + (size_t)slice * B_ROWS + rbase;
        pp[0]  = pr[0];
        pp[8]  = pr[1];
        pp[16] = pr[2];
        pp[24] = pr[3];
    }
}

// ---------------- final: combine + sigmoid ----------------
__global__ void final_kernel(const float* __restrict__ b3, float* __restrict__ out) {
    int row = blockIdx.x * 256 + threadIdx.x;
    if (row < B_ROWS) {
        float z = g_wide[row] + b3[0];
        #pragma unroll
        for (int s = 0; s < NSLICE; s++) z += g_part[(size_t)s * B_ROWS + row];
        out[row] = 1.0f / (1.0f + expf(-z));
    }
}

// ---------------- launch ----------------
extern "C" void kernel_launch(void* const* d_in, const int* in_sizes, int n_in,
                              void* d_out, int out_size) {
    const int*   sparse = (const int*)d_in[0];
    const float* dense  = (const float*)d_in[1];
    const float* wide_w = (const float*)d_in[2];
    const float* wide_b = (const float*)d_in[3];
    const float* emb    = (const float*)d_in[4];
    const float* W1     = (const float*)d_in[5];
    const float* b1     = (const float*)d_in[6];
    const float* W2     = (const float*)d_in[7];
    const float* b2     = (const float*)d_in[8];
    const float* W3     = (const float*)d_in[9];
    const float* b3     = (const float*)d_in[10];
    float* out = (float*)d_out;

    cudaFuncSetAttribute(gemm1_emb, cudaFuncAttributeMaxDynamicSharedMemorySize, SMEM_BYTES);
    cudaFuncSetAttribute(gemm2_tc, cudaFuncAttributeMaxDynamicSharedMemorySize, SMEM_BYTES);

    prep_all_kernel<<<PADW1_BLOCKS + CONVW2_BLOCKS + CONVEMB_BLOCKS + DENSEH_BLOCKS + WIDE_BLOCKS,
                      256>>>(W1, W2, sparse, dense, wide_w, wide_b, emb);

    __half* w2h;   cudaGetSymbolAddress((void**)&w2h, g_w2h);
    __half* h1;    cudaGetSymbolAddress((void**)&h1, g_h1);
    float* partp;  cudaGetSymbolAddress((void**)&partp, g_part);

    dim3 grid(H_DIM / 128, B_ROWS / 128);   // (8, 128) = 1024 CTAs
    // layer 1: A gathered from emb_h/dense_h, B = w1h; relu -> h1 fp16
    gemm1_emb<<<grid, 256, SMEM_BYTES>>>(sparse, b1, h1);
    // layer 2: K=1024, fused relu + W3 dot -> partials
    gemm2_tc<<<grid, 256, SMEM_BYTES>>>(h1, w2h, b2, W3, partp);
    final_kernel<<<(B_ROWS + 255) / 256, 256>>>(b3, out);
}

// round 16
// speedup vs baseline: 1.6365x; 1.0083x over previous
#include <cuda_runtime.h>
#include <cuda_fp16.h>
#include <cstdint>

// ---------------- problem constants ----------------
#define B_ROWS 16384
#define H_DIM  1024
#define DEEP_IN 205
#define K1_PAD 256          // W1 storage stride; live K = 208 (13 k16 steps)
#define ND_DIM 13

// Wide offsets (reference: cross = cross*F + s, F=3)
#define OFF_PAIR01  768
#define OFF_PAIR02  (768 + 65536)
#define OFF_PAIR12  (768 + 131072)
#define OFF_TRIPLE  (768 + 196608)
#define OFF_DENSE   16974592

#define NSLICE 16   // (H/128) * 2 wn strips

// ---------------- device scratch ----------------
__device__ __half g_emb_h[3 * 256 * 64];              // fp16 embedding tables
__device__ __half g_dense_h[(size_t)B_ROWS * 64];     // dense padded to 64 cols
__device__ __half g_w1h[(size_t)H_DIM * K1_PAD];
__device__ __half g_w2h[(size_t)H_DIM * H_DIM];
__device__ float  g_wide[B_ROWS];
__device__ __half g_h1[(size_t)B_ROWS * H_DIM];
__device__ float  g_part[NSLICE * B_ROWS];

// ---------------- helpers ----------------
__device__ __forceinline__ uint32_t smem_u32(const void* p) {
    uint32_t a;
    asm("{ .reg .u64 t; cvta.to.shared.u64 t, %1; cvt.u32.u64 %0, t; }" : "=r"(a) : "l"(p));
    return a;
}
__device__ __forceinline__ void cp_async16(uint32_t saddr, const void* gptr) {
    asm volatile("cp.async.cg.shared.global [%0], [%1], 16;\n" :: "r"(saddr), "l"(gptr));
}
__device__ __forceinline__ void cp_commit() { asm volatile("cp.async.commit_group;\n"); }

__device__ __forceinline__ void ldsm_x4(uint32_t& r0, uint32_t& r1, uint32_t& r2, uint32_t& r3,
                                        uint32_t addr) {
    asm volatile("ldmatrix.sync.aligned.m8n8.x4.shared.b16 {%0,%1,%2,%3}, [%4];"
                 : "=r"(r0), "=r"(r1), "=r"(r2), "=r"(r3) : "r"(addr));
}

// ---------------- prep-A: only gemm1's inputs (w1h, emb_h, dense_h) ----------------
#define PADW1_BLOCKS   1024    // 256*1024/256
#define CONVEMB_BLOCKS 96      // 3*256*64/(256*2)
#define DENSEH_BLOCKS  2048    // 16384*32 half2 / 256
#define PREPA_BLOCKS   (PADW1_BLOCKS + CONVEMB_BLOCKS + DENSEH_BLOCKS)

__global__ void prep_a_kernel(const float* __restrict__ W1,
                              const float* __restrict__ dense,
                              const float* __restrict__ emb) {
    int b = blockIdx.x;
    if (b < PADW1_BLOCKS) {
        int idx = b * 256 + threadIdx.x;
        int n = idx >> 8;
        int k = idx & 255;
        g_w1h[idx] = __float2half((k < DEEP_IN) ? W1[n * DEEP_IN + k] : 0.0f);
        return;
    }
    b -= PADW1_BLOCKS;
    if (b < CONVEMB_BLOCKS) {
        int idx = b * 256 + threadIdx.x;
        float2 v = *reinterpret_cast<const float2*>(emb + idx * 2);
        *reinterpret_cast<__half2*>(g_emb_h + idx * 2) = __floats2half2_rn(v.x, v.y);
        return;
    }
    b -= CONVEMB_BLOCKS;
    {
        int idx = b * 256 + threadIdx.x;        // one half2 (2 cols)
        int row = idx >> 5;
        int c2 = idx & 31;
        int c0 = c2 * 2, c1 = c0 + 1;
        float v0 = (c0 < ND_DIM) ? dense[row * ND_DIM + c0] : 0.0f;
        float v1 = (c1 < ND_DIM) ? dense[row * ND_DIM + c1] : 0.0f;
        *reinterpret_cast<__half2*>(g_dense_h + (size_t)row * 64 + c0) = __floats2half2_rn(v0, v1);
    }
}

// ---------------- shared GEMM config ----------------
#define BK 64
#define ROWB 144
#define A_BYTES (128 * ROWB)               // 18432
#define STAGE_BYTES (2 * A_BYTES)          // 36864
#define NSTAGE 3
#define SMEM_BYTES (NSTAGE * STAGE_BYTES)  // 110592

#define MMA_BLOCK(acc, af, bf) \
    _Pragma("unroll") \
    for (int im = 0; im < 2; im++) \
        _Pragma("unroll") \
        for (int jn = 0; jn < 8; jn++) { \
            asm volatile( \
                "mma.sync.aligned.m16n8k16.row.col.f32.f16.f16.f32 " \
                "{%0,%1,%2,%3},{%4,%5,%6,%7},{%8,%9},{%0,%1,%2,%3};\n" \
                : "+f"((acc)[im][jn][0]), "+f"((acc)[im][jn][1]), \
                  "+f"((acc)[im][jn][2]), "+f"((acc)[im][jn][3]) \
                : "r"((af)[im][0]), "r"((af)[im][1]), "r"((af)[im][2]), "r"((af)[im][3]), \
                  "r"((bf)[jn][0]), "r"((bf)[jn][1])); \
        }

// ---------------- gemm1 + prep-B combined launch ----------------
// bid < 1024: gemm1 tile CTA (bm = bid>>3, bn = bid&7), A gathered from tables.
// bid 1024..1151: w2h conversion (128 CTAs).
// bid 1152..1183: wide scalar (32 CTAs, 2 rows/thread).
// Total 1184 CTAs = exactly 4 waves of 296 slots; prep-B fills gemm1's tail.
// Kernel boundary is the barrier — no flags, no spinning (R13 lesson).
#define G1_TILES 1184
#define W2H_CTAS 128
#define WIDE_CTAS 32

__global__ __launch_bounds__(256, 2)
void gemm1_emb(const int* __restrict__ sparse,
               const float* __restrict__ bias,
               __half* __restrict__ C,
               const float* __restrict__ W2,
               const float* __restrict__ dense,
               const float* __restrict__ wide_w,
               const float* __restrict__ wide_b) {
    extern __shared__ char smem[];
    int bid = blockIdx.x;
    int tid = threadIdx.x;

    // ---- prep-B region ----
    if (bid >= 1024) {
        int p = bid - 1024;
        if (p < W2H_CTAS) {
            const int stride = W2H_CTAS * 256;
            for (int idx = p * 256 + tid; idx < H_DIM * H_DIM / 2; idx += stride) {
                float2 v = *reinterpret_cast<const float2*>(W2 + idx * 2);
                *reinterpret_cast<__half2*>(g_w2h + idx * 2) = __floats2half2_rn(v.x, v.y);
            }
        } else {
            const int stride = WIDE_CTAS * 256;
            for (int row = (p - W2H_CTAS) * 256 + tid; row < B_ROWS; row += stride) {
                int s0 = sparse[row * 3 + 0];
                int s1 = sparse[row * 3 + 1];
                int s2 = sparse[row * 3 + 2];
                float w = wide_b[0];
                w += wide_w[s0] + wide_w[256 + s1] + wide_w[512 + s2];
                w += wide_w[OFF_PAIR01 + s0 * 3 + s1];
                w += wide_w[OFF_PAIR02 + s0 * 3 + s2];
                w += wide_w[OFF_PAIR12 + s1 * 3 + s2];
                w += wide_w[OFF_TRIPLE + (s0 * 3 + s1) * 3 + s2];
                const float* dw = wide_w + OFF_DENSE;
                float acc = 0.0f;
                #pragma unroll
                for (int j = 0; j < ND_DIM; j++) acc += dense[row * ND_DIM + j] * dw[j];
                g_wide[row] = w + acc;
            }
        }
        return;
    }

    // ---- gemm1 tile ----
    uint32_t sb = smem_u32(smem);
    int bm = bid >> 3, bn = bid & 7;
    int lane = tid & 31;
    int warp = tid >> 5;
    int wm = warp & 3;
    int wn = warp >> 2;

    int lrow = lane & 7;
    int lmat = lane >> 3;
    uint32_t aoff0 = (uint32_t)((wm * 32 + ((lmat & 1) << 3) + lrow) * ROWB + ((lmat >> 1) << 4));
    uint32_t boff0 = (uint32_t)((wn * 64 + ((lmat >> 1) << 3) + lrow) * ROWB + ((lmat & 1) << 4));

    float acc[2][8][4];
    #pragma unroll
    for (int i = 0; i < 2; i++)
        #pragma unroll
        for (int j = 0; j < 8; j++)
            #pragma unroll
            for (int q = 0; q < 4; q++) acc[i][j][q] = 0.0f;

    const __half* Bg = g_w1h + (size_t)(bn * 128) * K1_PAD;

    auto load_stage = [&](int slot, int kt_i) {
        uint32_t sA = sb + slot * STAGE_BYTES;
        uint32_t sB = sA + A_BYTES;
        #pragma unroll
        for (int i = 0; i < 8; i++) {
            int idx = i * 256 + tid;
            if (idx < 1024) {
                int r = idx >> 3, c = idx & 7;
                const __half* src;
                if (kt_i < 3) {
                    int s = sparse[(bm * 128 + r) * 3 + kt_i];
                    src = g_emb_h + ((kt_i << 8) + s) * 64 + c * 8;
                } else {
                    src = g_dense_h + (size_t)(bm * 128 + r) * 64 + c * 8;
                }
                cp_async16(sA + r * ROWB + c * 16, src);
            } else {
                int j = idx - 1024;
                int r = j >> 3, c = j & 7;
                cp_async16(sB + r * ROWB + c * 16, Bg + (size_t)r * K1_PAD + kt_i * BK + c * 8);
            }
        }
        cp_commit();
    };

    load_stage(0, 0);
    load_stage(1, 1);

    int slot = 0, slot2 = 2;
    for (int kt = 0; kt < 4; kt++) {
        asm volatile("cp.async.wait_group 1;\n" ::: "memory");
        __syncthreads();

        if (kt + 2 < 4) load_stage(slot2, kt + 2);
        else cp_commit();

        uint32_t sA = sb + slot * STAGE_BYTES;
        uint32_t sB = sA + A_BYTES;

        int ks_n = (kt < 3) ? 4 : 1;     // tail tile: only k16 step 0 is live
        for (int ks = 0; ks < ks_n; ks++) {
            uint32_t af[2][4];
            #pragma unroll
            for (int im = 0; im < 2; im++)
                ldsm_x4(af[im][0], af[im][1], af[im][2], af[im][3],
                        sA + aoff0 + im * (16 * ROWB) + ks * 32);
            uint32_t bf[8][2];
            #pragma unroll
            for (int p = 0; p < 4; p++) {
                uint32_t q0, q1, q2, q3;
                ldsm_x4(q0, q1, q2, q3, sB + boff0 + p * (16 * ROWB) + ks * 32);
                bf[2 * p][0] = q0; bf[2 * p][1] = q1;
                bf[2 * p + 1][0] = q2; bf[2 * p + 1][1] = q3;
            }
            MMA_BLOCK(acc, af, bf);
        }

        slot = (slot == NSTAGE - 1) ? 0 : slot + 1;
        slot2 = (slot2 == NSTAGE - 1) ? 0 : slot2 + 1;
    }

    int nbase = bn * 128 + wn * 64 + 2 * (lane & 3);
    #pragma unroll
    for (int im = 0; im < 2; im++) {
        #pragma unroll
        for (int jn = 0; jn < 8; jn++) {
            int m0 = bm * 128 + wm * 32 + im * 16 + (lane >> 2);
            int n0 = nbase + jn * 8;
            float bv0 = __ldg(bias + n0), bv1 = __ldg(bias + n0 + 1);
            float v0 = fmaxf(acc[im][jn][0] + bv0, 0.0f);
            float v1 = fmaxf(acc[im][jn][1] + bv1, 0.0f);
            float v2 = fmaxf(acc[im][jn][2] + bv0, 0.0f);
            float v3 = fmaxf(acc[im][jn][3] + bv1, 0.0f);
            *reinterpret_cast<__half2*>(&C[(size_t)m0 * H_DIM + n0]) = __floats2half2_rn(v0, v1);
            *reinterpret_cast<__half2*>(&C[(size_t)(m0 + 8) * H_DIM + n0]) = __floats2half2_rn(v2, v3);
        }
    }
}

// ---------------- layer-2 GEMM (champion structure, unchanged) ----------------
__global__ __launch_bounds__(256, 2)
void gemm2_tc(const __half* __restrict__ A,
              const __half* __restrict__ Bm,
              const float* __restrict__ bias,
              const float* __restrict__ W3,
              float* __restrict__ part) {
    extern __shared__ char smem[];
    uint32_t sb = smem_u32(smem);

    int tid = threadIdx.x;
    int lane = tid & 31;
    int warp = tid >> 5;
    int wm = warp & 3;
    int wn = warp >> 2;
    int bn = blockIdx.x, bm = blockIdx.y;

    const __half* Ag = A + (size_t)(bm * 128) * H_DIM;
    const __half* Bg = Bm + (size_t)(bn * 128) * H_DIM;

    int lrow = lane & 7;
    int lmat = lane >> 3;
    uint32_t aoff0 = (uint32_t)((wm * 32 + ((lmat & 1) << 3) + lrow) * ROWB + ((lmat >> 1) << 4));
    uint32_t boff0 = (uint32_t)((wn * 64 + ((lmat >> 1) << 3) + lrow) * ROWB + ((lmat & 1) << 4));

    float acc[2][8][4];
    #pragma unroll
    for (int i = 0; i < 2; i++)
        #pragma unroll
        for (int j = 0; j < 8; j++)
            #pragma unroll
            for (int q = 0; q < 4; q++) acc[i][j][q] = 0.0f;

    auto load_stage = [&](int slot, int k0) {
        uint32_t sA = sb + slot * STAGE_BYTES;
        uint32_t sB = sA + A_BYTES;
        #pragma unroll
        for (int i = 0; i < 8; i++) {
            int idx = i * 256 + tid;
            if (idx < 1024) {
                int r = idx >> 3, c = idx & 7;
                cp_async16(sA + r * ROWB + c * 16, Ag + (size_t)r * H_DIM + k0 + c * 8);
            } else {
                int j = idx - 1024;
                int r = j >> 3, c = j & 7;
                cp_async16(sB + r * ROWB + c * 16, Bg + (size_t)r * H_DIM + k0 + c * 8);
            }
        }
        cp_commit();
    };

    load_stage(0, 0);
    load_stage(1, BK);

    const int KT = H_DIM / BK;   // 16
    int slot = 0, slot2 = 2;
    for (int kt = 0; kt < KT; kt++) {
        asm volatile("cp.async.wait_group 1;\n" ::: "memory");
        __syncthreads();

        if (kt + 2 < KT) load_stage(slot2, (kt + 2) * BK);
        else cp_commit();

        uint32_t sA = sb + slot * STAGE_BYTES;
        uint32_t sB = sA + A_BYTES;

        #pragma unroll
        for (int ks = 0; ks < 4; ks++) {
            uint32_t af[2][4];
            #pragma unroll
            for (int im = 0; im < 2; im++)
                ldsm_x4(af[im][0], af[im][1], af[im][2], af[im][3],
                        sA + aoff0 + im * (16 * ROWB) + ks * 32);
            uint32_t bf[8][2];
            #pragma unroll
            for (int p = 0; p < 4; p++) {
                uint32_t q0, q1, q2, q3;
                ldsm_x4(q0, q1, q2, q3, sB + boff0 + p * (16 * ROWB) + ks * 32);
                bf[2 * p][0] = q0; bf[2 * p][1] = q1;
                bf[2 * p + 1][0] = q2; bf[2 * p + 1][1] = q3;
            }
            MMA_BLOCK(acc, af, bf);
        }

        slot = (slot == NSTAGE - 1) ? 0 : slot + 1;
        slot2 = (slot2 == NSTAGE - 1) ? 0 : slot2 + 1;
    }

    int nbase = bn * 128 + wn * 64 + 2 * (lane & 3);
    float pr[4] = {0.0f, 0.0f, 0.0f, 0.0f};
    #pragma unroll
    for (int jn = 0; jn < 8; jn++) {
        int n0 = nbase + jn * 8;
        float bv0 = __ldg(bias + n0), bv1 = __ldg(bias + n0 + 1);
        float w0 = __ldg(W3 + n0), w1 = __ldg(W3 + n0 + 1);
        #pragma unroll
        for (int im = 0; im < 2; im++) {
            float v0 = fmaxf(acc[im][jn][0] + bv0, 0.0f);
            float v1 = fmaxf(acc[im][jn][1] + bv1, 0.0f);
            float v2 = fmaxf(acc[im][jn][2] + bv0, 0.0f);
            float v3 = fmaxf(acc[im][jn][3] + bv1, 0.0f);
            pr[2 * im + 0] += v0 * w0 + v1 * w1;
            pr[2 * im + 1] += v2 * w0 + v3 * w1;
        }
    }
    #pragma unroll
    for (int q = 0; q < 4; q++) {
        pr[q] += __shfl_xor_sync(0xffffffffu, pr[q], 1);
        pr[q] += __shfl_xor_sync(0xffffffffu, pr[q], 2);
    }
    if ((lane & 3) == 0) {
        int slice = bn * 2 + wn;
        int rbase = bm * 128 + wm * 32 + (lane >> 2);
        float* pp = part + (size_t)slice * B_ROWS + rbase;
        pp[0]  = pr[0];
        pp[8]  = pr[1];
        pp[16] = pr[2];
        pp[24] = pr[3];
    }
}

// ---------------- final: combine + sigmoid (128 CTAs for more MLP) ----------------
__global__ void final_kernel(const float* __restrict__ b3, float* __restrict__ out) {
    int row = blockIdx.x * 128 + threadIdx.x;
    float z = g_wide[row] + b3[0];
    #pragma unroll
    for (int s = 0; s < NSLICE; s++) z += g_part[(size_t)s * B_ROWS + row];
    out[row] = 1.0f / (1.0f + expf(-z));
}

// ---------------- launch ----------------
extern "C" void kernel_launch(void* const* d_in, const int* in_sizes, int n_in,
                              void* d_out, int out_size) {
    const int*   sparse = (const int*)d_in[0];
    const float* dense  = (const float*)d_in[1];
    const float* wide_w = (const float*)d_in[2];
    const float* wide_b = (const float*)d_in[3];
    const float* emb    = (const float*)d_in[4];
    const float* W1     = (const float*)d_in[5];
    const float* b1     = (const float*)d_in[6];
    const float* W2     = (const float*)d_in[7];
    const float* b2     = (const float*)d_in[8];
    const float* W3     = (const float*)d_in[9];
    const float* b3     = (const float*)d_in[10];
    float* out = (float*)d_out;

    cudaFuncSetAttribute(gemm1_emb, cudaFuncAttributeMaxDynamicSharedMemorySize, SMEM_BYTES);
    cudaFuncSetAttribute(gemm2_tc, cudaFuncAttributeMaxDynamicSharedMemorySize, SMEM_BYTES);

    // prep-A: only gemm1's inputs
    prep_a_kernel<<<PREPA_BLOCKS, 256>>>(W1, dense, emb);

    __half* w2h;   cudaGetSymbolAddress((void**)&w2h, g_w2h);
    __half* h1;    cudaGetSymbolAddress((void**)&h1, g_h1);
    float* partp;  cudaGetSymbolAddress((void**)&partp, g_part);

    // gemm1 tiles + prep-B (w2h, wide) in one launch: prep-B fills the tail wave
    gemm1_emb<<<G1_TILES, 256, SMEM_BYTES>>>(sparse, b1, h1, W2, dense, wide_w, wide_b);
    // layer 2: K=1024, fused relu + W3 dot -> partials
    dim3 grid2(H_DIM / 128, B_ROWS / 128);   // (8, 128)
    gemm2_tc<<<grid2, 256, SMEM_BYTES>>>(h1, w2h, b2, W3, partp);
    final_kernel<<<B_ROWS / 128, 128>>>(b3, out);
}